// round 16
// baseline (speedup 1.0000x reference)
#include <cuda_runtime.h>
#include <cuda_bf16.h>

#define TSEQ   2048
#define BATCH  4096
#define HDIM   32
#define STAGE  16
#define NSTAGE (TSEQ / STAGE)
#define ROWS   8          // rows per group (n8 MMA)
#define GRP    2          // independent batch groups per warp
#define WROWS  (ROWS * GRP)
#define NWARPS 4
#define XPAD   17         // x stage-dim pad (bank spread: row stride 272B)
#define HPAD   40         // h row pad in halves (80B stride, bank spread)

typedef unsigned int   u32;
typedef unsigned short u16;

// ---------- activations ----------
__device__ __forceinline__ float tanhf_fast(float x) {
    float y; asm("tanh.approx.f32 %0, %1;" : "=f"(y) : "f"(x)); return y;
}
// sigmoid(x) = 0.5*tanh(x/2) + 0.5 ; the /2 pre-folded into weights+bias.
__device__ __forceinline__ float sig_from_half(float xh) {
    return fmaf(0.5f, tanhf_fast(xh), 0.5f);
}

// ---------- bf16 split helpers ----------
__device__ __forceinline__ u32 pack_hi_trunc(float e0, float e1) {
    return (__float_as_uint(e0) >> 16) | (__float_as_uint(e1) & 0xFFFF0000u);
}
__device__ __forceinline__ float trunc_bf(float a) {
    return __uint_as_float(__float_as_uint(a) & 0xFFFF0000u);
}
__device__ __forceinline__ u32 pack_bf16_rn(float e0, float e1) {
    u32 r; asm("cvt.rn.bf16x2.f32 %0, %1, %2;" : "=r"(r) : "f"(e1), "f"(e0)); return r;
}
__device__ __forceinline__ u16 bf16_bits(float a) {
    __nv_bfloat16 v = __float2bfloat16(a);
    return *reinterpret_cast<u16*>(&v);
}

// ---------- async copy ----------
__device__ __forceinline__ void cp_async4(u32 saddr, const void* gaddr) {
    asm volatile("cp.async.ca.shared.global [%0], [%1], 4;" :: "r"(saddr), "l"(gaddr));
}
__device__ __forceinline__ void cp_async_commit() { asm volatile("cp.async.commit_group;"); }
__device__ __forceinline__ void cp_async_wait0()  { asm volatile("cp.async.wait_group 0;"); }
// converged warp: program order covers STS->LDS; fence the compiler only
__device__ __forceinline__ void step_fence() { asm volatile("" ::: "memory"); }

// m16n8k16 bf16 MMA, fp32 accumulate (D += A @ B)
#define MMA16816(d, a, b0, b1)                                               \
    asm volatile("mma.sync.aligned.m16n8k16.row.col.f32.bf16.bf16.f32 "     \
        "{%0,%1,%2,%3}, {%4,%5,%6,%7}, {%8,%9}, {%0,%1,%2,%3};"             \
        : "+f"((d)[0]), "+f"((d)[1]), "+f"((d)[2]), "+f"((d)[3])            \
        : "r"((a)[0]), "r"((a)[1]), "r"((a)[2]), "r"((a)[3]), "r"(b0), "r"(b1))

// One warp = TWO independent 8-row batch groups through all 2048 steps.
// A-fragments (split-bf16 W_hh, 128 regs) are SHARED by both groups; group
// A's MUFU activation tail overlaps group B's tensor-pipe MMA latency.
__global__ void __launch_bounds__(128, 1)
lstm_mma_kernel(const float* __restrict__ x,
                const float* __restrict__ W_ih,
                const float* __restrict__ W_hh,
                const float* __restrict__ b_ih,
                const float* __restrict__ b_hh,
                float* __restrict__ out)
{
    __shared__ __align__(16) float  xs[NWARPS][2][WROWS][XPAD][4];
    __shared__ __align__(4)  u16    hhi[NWARPS][GRP][ROWS][HPAD];
    __shared__ __align__(4)  u16    hlo[NWARPS][GRP][ROWS][HPAD];
    __shared__ __align__(16) float4 wxb[4 * HDIM];   // {wx0,wx1,wx2,bias} per gate row

    const int tid  = threadIdx.x;
    const int wid  = tid >> 5;
    const int lane = tid & 31;
    const int g    = lane >> 2;   // groupID
    const int t    = lane & 3;    // threadID_in_group

    // input-weight + bias table (sigmoid rows pre-scaled by 0.5)
    {
        int m = tid;              // 128 threads, 128 gate rows
        float s = ((m >> 5) == 2) ? 1.0f : 0.5f;
        wxb[m] = make_float4(s * W_ih[m * 3 + 0], s * W_ih[m * 3 + 1],
                             s * W_ih[m * 3 + 2], s * (b_ih[m] + b_hh[m]));
    }
    // zero h arrays (h0 = 0), both groups
    for (int i2 = lane; i2 < GRP * ROWS * HPAD; i2 += 32) {
        int gp = i2 / (ROWS * HPAD);
        int r  = (i2 / HPAD) % ROWS;
        int u  = i2 % HPAD;
        hhi[wid][gp][r][u] = 0;
        hlo[wid][gp][r][u] = 0;
    }
    __syncthreads();

    // ---- static A-fragments: W_hh split hi/lo, sigmoid rows *0.5 ----
    u32 Ahi[8][2][4], Alo[8][2][4];
#pragma unroll
    for (int T = 0; T < 8; T++) {
#pragma unroll
        for (int Kt = 0; Kt < 2; Kt++) {
            int k0 = 16 * Kt + 2 * t;
#pragma unroll
            for (int r = 0; r < 4; r++) {
                int m = 16 * T + g + ((r & 1) ? 8 : 0);
                int k = k0 + ((r >> 1) ? 8 : 0);
                float s  = ((m >> 5) == 2) ? 1.0f : 0.5f;
                float w0 = s * W_hh[m * HDIM + k];
                float w1 = s * W_hh[m * HDIM + k + 1];
                Ahi[T][Kt][r] = pack_hi_trunc(w0, w1);
                Alo[T][Kt][r] = pack_bf16_rn(w0 - trunc_bf(w0), w1 - trunc_bf(w1));
            }
        }
    }

    const int row0 = (blockIdx.x * NWARPS + wid) * WROWS;
    u32 xbase[2];
    xbase[0] = (u32)__cvta_generic_to_shared(&xs[wid][0][0][0][0]);
    xbase[1] = (u32)__cvta_generic_to_shared(&xs[wid][1][0][0][0]);

    // ---- stage 0 of x (WROWS*STAGE*3 = 768 elems, 24 per lane, exact) ----
#pragma unroll
    for (int it = 0; it < 24; it++) {
        int idx = it * 32 + lane;
        int b   = idx / (STAGE * 3);
        int rem = idx % (STAGE * 3);
        int ts  = rem / 3, i = rem % 3;
        cp_async4(xbase[0] + (u32)(((b * XPAD + ts) * 4 + i) * 4),
                  x + (size_t)(row0 + b) * TSEQ * 3 + rem);
    }
    cp_async_commit();
    cp_async_wait0();
    __syncwarp();

    float cst[GRP][8];
#pragma unroll
    for (int gp = 0; gp < GRP; gp++)
#pragma unroll
        for (int i = 0; i < 8; i++) cst[gp][i] = 0.0f;

    int buf = 0;
#pragma unroll 1
    for (int s = 0; s < NSTAGE; s++) {
        // prefetch next stage (fire and forget)
        if (s + 1 < NSTAGE) {
#pragma unroll
            for (int it = 0; it < 24; it++) {
                int idx = it * 32 + lane;
                int b   = idx / (STAGE * 3);
                int rem = idx % (STAGE * 3);
                int ts  = rem / 3, i = rem % 3;
                cp_async4(xbase[buf ^ 1] + (u32)(((b * XPAD + ts) * 4 + i) * 4),
                          x + (size_t)(row0 + b) * TSEQ * 3
                            + (size_t)(s + 1) * STAGE * 3 + rem);
            }
            cp_async_commit();
        }

#pragma unroll 1
        for (int tt = 0; tt < STAGE; tt++) {
            // ---- B fragments for BOTH groups ----
            u32 bh[GRP][2][2], bl[GRP][2][2];
#pragma unroll
            for (int gp = 0; gp < GRP; gp++)
#pragma unroll
                for (int Kt = 0; Kt < 2; Kt++) {
                    int k = 16 * Kt + 2 * t;
                    bh[gp][Kt][0] = *(const u32*)&hhi[wid][gp][g][k];
                    bh[gp][Kt][1] = *(const u32*)&hhi[wid][gp][g][k + 8];
                    bl[gp][Kt][0] = *(const u32*)&hlo[wid][gp][g][k];
                    bl[gp][Kt][1] = *(const u32*)&hlo[wid][gp][g][k + 8];
                }

            // ---- affine + bias seeds D for both groups ----
            float d[GRP][8][4];
#pragma unroll
            for (int gp = 0; gp < GRP; gp++) {
                float4 xa = *(const float4*)&xs[wid][buf][gp * ROWS + 2 * t][tt][0];
                float4 xb = *(const float4*)&xs[wid][buf][gp * ROWS + 2 * t + 1][tt][0];
#pragma unroll
                for (int T = 0; T < 8; T++) {
#pragma unroll
                    for (int h2 = 0; h2 < 2; h2++) {
                        float4 wv = wxb[16 * T + 8 * h2 + g];
                        d[gp][T][2 * h2 + 0] = fmaf(wv.x, xa.x, fmaf(wv.y, xa.y, fmaf(wv.z, xa.z, wv.w)));
                        d[gp][T][2 * h2 + 1] = fmaf(wv.x, xb.x, fmaf(wv.y, xb.y, fmaf(wv.z, xb.z, wv.w)));
                    }
                }
            }

            // ---- 96 HMMA, groups interleaved T-wise (16 indep. chains) ----
#pragma unroll
            for (int T = 0; T < 8; T++) {
#pragma unroll
                for (int Kt = 0; Kt < 2; Kt++) {
                    MMA16816(d[0][T], Ahi[T][Kt], bh[0][Kt][0], bh[0][Kt][1]);
                    MMA16816(d[1][T], Ahi[T][Kt], bh[1][Kt][0], bh[1][Kt][1]);
                    MMA16816(d[0][T], Alo[T][Kt], bh[0][Kt][0], bh[0][Kt][1]);
                    MMA16816(d[1][T], Alo[T][Kt], bh[1][Kt][0], bh[1][Kt][1]);
                    MMA16816(d[0][T], Ahi[T][Kt], bl[0][Kt][0], bl[0][Kt][1]);
                    MMA16816(d[1][T], Ahi[T][Kt], bl[1][Kt][0], bl[1][Kt][1]);
                }
            }

            // ---- activations group 0 (overlaps group 1's MMA tail), then 1 ----
#pragma unroll
            for (int gp = 0; gp < GRP; gp++) {
#pragma unroll
                for (int Tp = 0; Tp < 2; Tp++) {
#pragma unroll
                    for (int h2 = 0; h2 < 2; h2++) {
                        int u = 16 * Tp + 8 * h2 + g;
#pragma unroll
                        for (int dl = 0; dl < 2; dl++) {
                            int ci = (Tp * 2 + h2) * 2 + dl;
                            float iP = d[gp][0 + Tp][2 * h2 + dl];
                            float fP = d[gp][2 + Tp][2 * h2 + dl];
                            float gP = d[gp][4 + Tp][2 * h2 + dl];
                            float oP = d[gp][6 + Tp][2 * h2 + dl];
                            float ig = sig_from_half(iP);
                            float fg = sig_from_half(fP);
                            float gg = tanhf_fast(gP);
                            float og = sig_from_half(oP);
                            cst[gp][ci] = fmaf(fg, cst[gp][ci], ig * gg);
                            float hv = og * tanhf_fast(cst[gp][ci]);
                            int r = 2 * t + dl;
                            u32 hb = __float_as_uint(hv);
                            hhi[wid][gp][r][u] = (u16)(hb >> 16);
                            hlo[wid][gp][r][u] =
                                bf16_bits(hv - __uint_as_float(hb & 0xFFFF0000u));
                        }
                    }
                }
            }
            step_fence();
        }

        if (s + 1 < NSTAGE) {
            cp_async_wait0();
            __syncwarp();
            buf ^= 1;
        }
    }

    // ---- final h reconstructed from smem hi+lo (error ~2^-16, negligible) ----
    __syncwarp();
    for (int idx = lane; idx < WROWS * HDIM; idx += 32) {
        int r  = idx >> 5;          // 0..15
        int u  = idx & 31;
        int gp = r >> 3;
        int rr = r & 7;
        float hi = __uint_as_float((u32)hhi[wid][gp][rr][u] << 16);
        float lo = __uint_as_float((u32)hlo[wid][gp][rr][u] << 16);
        out[(size_t)(row0 + r) * HDIM + u] = hi + lo;
    }
}

extern "C" void kernel_launch(void* const* d_in, const int* in_sizes, int n_in,
                              void* d_out, int out_size)
{
    const float* x    = (const float*)d_in[0];
    const float* W_ih = (const float*)d_in[1];
    const float* W_hh = (const float*)d_in[2];
    const float* b_ih = (const float*)d_in[3];
    const float* b_hh = (const float*)d_in[4];
    float* out = (float*)d_out;

    // 64 blocks x 128 threads: 256 warps x 16 rows = 4096
    lstm_mma_kernel<<<BATCH / (NWARPS * WROWS), NWARPS * 32>>>(
        x, W_ih, W_hh, b_ih, b_hh, out);
}

// round 17
// speedup vs baseline: 2.1408x; 2.1408x over previous
#include <cuda_runtime.h>
#include <cuda_bf16.h>

#define TSEQ   2048
#define BATCH  4096
#define HDIM   32
#define STAGE  16
#define NSTAGE (TSEQ / STAGE)
#define ROWS   8          // batch rows per pair (n8 MMA)
#define NPAIR  2          // warp pairs per block
#define XPAD   17         // x stage-dim pad (bank spread)
#define HPAD   40         // h row pad in halves (80B stride, bank spread)

typedef unsigned int   u32;
typedef unsigned short u16;

// ---------- activations ----------
__device__ __forceinline__ float tanhf_fast(float x) {
    float y; asm("tanh.approx.f32 %0, %1;" : "=f"(y) : "f"(x)); return y;
}
// sigmoid(x) = 0.5*tanh(x/2) + 0.5 ; the /2 pre-folded into weights+bias.
__device__ __forceinline__ float sig_from_half(float xh) {
    return fmaf(0.5f, tanhf_fast(xh), 0.5f);
}

// ---------- bf16 split helpers ----------
__device__ __forceinline__ u32 pack_hi_trunc(float e0, float e1) {
    return (__float_as_uint(e0) >> 16) | (__float_as_uint(e1) & 0xFFFF0000u);
}
__device__ __forceinline__ float trunc_bf(float a) {
    return __uint_as_float(__float_as_uint(a) & 0xFFFF0000u);
}
__device__ __forceinline__ u32 pack_bf16_rn(float e0, float e1) {
    u32 r; asm("cvt.rn.bf16x2.f32 %0, %1, %2;" : "=r"(r) : "f"(e1), "f"(e0)); return r;
}
__device__ __forceinline__ u16 bf16_bits(float a) {
    __nv_bfloat16 v = __float2bfloat16(a);
    return *reinterpret_cast<u16*>(&v);
}

// ---------- async copy ----------
__device__ __forceinline__ void cp_async4(u32 saddr, const void* gaddr) {
    asm volatile("cp.async.ca.shared.global [%0], [%1], 4;" :: "r"(saddr), "l"(gaddr));
}
__device__ __forceinline__ void cp_async_commit() { asm volatile("cp.async.commit_group;"); }
__device__ __forceinline__ void cp_async_wait0()  { asm volatile("cp.async.wait_group 0;"); }
// 64-thread named barrier between the two warps of a pair (ids 1,2)
__device__ __forceinline__ void pair_bar(int id) {
    asm volatile("bar.sync %0, 64;" :: "r"(id) : "memory");
}

// m16n8k16 bf16 MMA, fp32 accumulate (D += A @ B)
#define MMA16816(d, a, b0, b1)                                               \
    asm volatile("mma.sync.aligned.m16n8k16.row.col.f32.bf16.bf16.f32 "     \
        "{%0,%1,%2,%3}, {%4,%5,%6,%7}, {%8,%9}, {%0,%1,%2,%3};"             \
        : "+f"((d)[0]), "+f"((d)[1]), "+f"((d)[2]), "+f"((d)[3])            \
        : "r"((a)[0]), "r"((a)[1]), "r"((a)[2]), "r"((a)[3]), "r"(b0), "r"(b1))

// Warp-pair decomposition: the two warps of a pair share 8 batch rows.
// Warp half=0 computes units 0-15 (T-tiles 0,2,4,6), half=1 units 16-31
// (T-tiles 1,3,5,7). A-fragments halve to 64 regs; both warps read the full
// h (hi/lo bf16 in smem) and write disjoint unit halves, synchronized by one
// 64-thread named barrier per step.
__global__ void __launch_bounds__(128, 2)
lstm_mma_kernel(const float* __restrict__ x,
                const float* __restrict__ W_ih,
                const float* __restrict__ W_hh,
                const float* __restrict__ b_ih,
                const float* __restrict__ b_hh,
                float* __restrict__ out)
{
    __shared__ __align__(16) float  xs[NPAIR][2][ROWS][XPAD][4];
    __shared__ __align__(4)  u16    hhi[NPAIR][ROWS][HPAD];
    __shared__ __align__(4)  u16    hlo[NPAIR][ROWS][HPAD];
    __shared__ __align__(16) float4 wxb[4 * HDIM];   // {wx0,wx1,wx2,bias} per gate row

    const int tid  = threadIdx.x;
    const int wid  = tid >> 5;
    const int lane = tid & 31;
    const int pair = wid >> 1;    // 0,1
    const int half = wid & 1;     // unit half
    const int g    = lane >> 2;   // groupID
    const int t    = lane & 3;    // threadID_in_group

    // input-weight + bias table (sigmoid rows pre-scaled by 0.5)
    {
        int m = tid;              // 128 threads, 128 gate rows
        float s = ((m >> 5) == 2) ? 1.0f : 0.5f;
        wxb[m] = make_float4(s * W_ih[m * 3 + 0], s * W_ih[m * 3 + 1],
                             s * W_ih[m * 3 + 2], s * (b_ih[m] + b_hh[m]));
    }
    // zero h arrays (h0 = 0)
    for (int i2 = tid; i2 < NPAIR * ROWS * HPAD; i2 += 128) {
        int p = i2 / (ROWS * HPAD);
        int r = (i2 / HPAD) % ROWS;
        int u = i2 % HPAD;
        hhi[p][r][u] = 0;
        hlo[p][r][u] = 0;
    }
    __syncthreads();

    // ---- static A-fragments for THIS warp's 4 T-tiles (T = 2*Tl + half) ----
    u32 Ahi[4][2][4], Alo[4][2][4];
#pragma unroll
    for (int Tl = 0; Tl < 4; Tl++) {
        int T = 2 * Tl + half;
#pragma unroll
        for (int Kt = 0; Kt < 2; Kt++) {
            int k0 = 16 * Kt + 2 * t;
#pragma unroll
            for (int r = 0; r < 4; r++) {
                int m = 16 * T + g + ((r & 1) ? 8 : 0);
                int k = k0 + ((r >> 1) ? 8 : 0);
                float s  = ((m >> 5) == 2) ? 1.0f : 0.5f;
                float w0 = s * W_hh[m * HDIM + k];
                float w1 = s * W_hh[m * HDIM + k + 1];
                Ahi[Tl][Kt][r] = pack_hi_trunc(w0, w1);
                Alo[Tl][Kt][r] = pack_bf16_rn(w0 - trunc_bf(w0), w1 - trunc_bf(w1));
            }
        }
    }

    const int row0   = blockIdx.x * (NPAIR * ROWS) + pair * ROWS;
    const int bar_id = 1 + pair;
    const int pl     = half * 32 + lane;      // 0..63 within pair

    u32 xbase[2];
    xbase[0] = (u32)__cvta_generic_to_shared(&xs[pair][0][0][0][0]);
    xbase[1] = (u32)__cvta_generic_to_shared(&xs[pair][1][0][0][0]);

    // ---- stage 0 of x: ROWS*STAGE*3 = 384 elems, pair-split (6 per lane) ----
#pragma unroll
    for (int it = 0; it < 6; it++) {
        int idx = it * 64 + pl;
        int b   = idx / (STAGE * 3);
        int rem = idx % (STAGE * 3);
        int ts  = rem / 3, i = rem % 3;
        cp_async4(xbase[0] + (u32)(((b * XPAD + ts) * 4 + i) * 4),
                  x + (size_t)(row0 + b) * TSEQ * 3 + rem);
    }
    cp_async_commit();
    cp_async_wait0();
    pair_bar(bar_id);

    float cst[4];
#pragma unroll
    for (int i = 0; i < 4; i++) cst[i] = 0.0f;

    int buf = 0;
#pragma unroll 1
    for (int s = 0; s < NSTAGE; s++) {
        // prefetch next stage (fire and forget, pair-split)
        if (s + 1 < NSTAGE) {
#pragma unroll
            for (int it = 0; it < 6; it++) {
                int idx = it * 64 + pl;
                int b   = idx / (STAGE * 3);
                int rem = idx % (STAGE * 3);
                int ts  = rem / 3, i = rem % 3;
                cp_async4(xbase[buf ^ 1] + (u32)(((b * XPAD + ts) * 4 + i) * 4),
                          x + (size_t)(row0 + b) * TSEQ * 3
                            + (size_t)(s + 1) * STAGE * 3 + rem);
            }
            cp_async_commit();
        }

#pragma unroll 1
        for (int tt = 0; tt < STAGE; tt++) {
            // ---- B fragments: full h (k=32), hi and lo ----
            u32 bh[2][2], bl[2][2];
#pragma unroll
            for (int Kt = 0; Kt < 2; Kt++) {
                int k = 16 * Kt + 2 * t;
                bh[Kt][0] = *(const u32*)&hhi[pair][g][k];
                bh[Kt][1] = *(const u32*)&hhi[pair][g][k + 8];
                bl[Kt][0] = *(const u32*)&hlo[pair][g][k];
                bl[Kt][1] = *(const u32*)&hlo[pair][g][k + 8];
            }

            // ---- affine + bias seeds D (cols = rows 2t, 2t+1) ----
            float4 xa = *(const float4*)&xs[pair][buf][2 * t][tt][0];
            float4 xb = *(const float4*)&xs[pair][buf][2 * t + 1][tt][0];
            float d[4][4];
#pragma unroll
            for (int Tl = 0; Tl < 4; Tl++) {
#pragma unroll
                for (int h2 = 0; h2 < 2; h2++) {
                    float4 wv = wxb[16 * (2 * Tl + half) + 8 * h2 + g];
                    d[Tl][2 * h2 + 0] = fmaf(wv.x, xa.x, fmaf(wv.y, xa.y, fmaf(wv.z, xa.z, wv.w)));
                    d[Tl][2 * h2 + 1] = fmaf(wv.x, xb.x, fmaf(wv.y, xb.y, fmaf(wv.z, xb.z, wv.w)));
                }
            }

            // ---- 24 HMMA: hi*hi + lo*hi + hi*lo, 4 independent T-chains ----
#pragma unroll
            for (int Tl = 0; Tl < 4; Tl++) {
#pragma unroll
                for (int Kt = 0; Kt < 2; Kt++) {
                    MMA16816(d[Tl], Ahi[Tl][Kt], bh[Kt][0], bh[Kt][1]);
                    MMA16816(d[Tl], Alo[Tl][Kt], bh[Kt][0], bh[Kt][1]);
                    MMA16816(d[Tl], Ahi[Tl][Kt], bl[Kt][0], bl[Kt][1]);
                }
            }

            // ---- activations: d[0]=i, d[1]=f, d[2]=g, d[3]=o for this half ----
#pragma unroll
            for (int h2 = 0; h2 < 2; h2++) {
                int u = 16 * half + 8 * h2 + g;
#pragma unroll
                for (int dl = 0; dl < 2; dl++) {
                    int ci = 2 * h2 + dl;
                    float ig = sig_from_half(d[0][2 * h2 + dl]);
                    float fg = sig_from_half(d[1][2 * h2 + dl]);
                    float gg = tanhf_fast(d[2][2 * h2 + dl]);
                    float og = sig_from_half(d[3][2 * h2 + dl]);
                    cst[ci] = fmaf(fg, cst[ci], ig * gg);
                    float hv = og * tanhf_fast(cst[ci]);
                    int r = 2 * t + dl;
                    u32 hb = __float_as_uint(hv);
                    hhi[pair][r][u] = (u16)(hb >> 16);
                    hlo[pair][r][u] = bf16_bits(hv - __uint_as_float(hb & 0xFFFF0000u));
                }
            }
            // pair barrier: partner's h half visible before next step's B reads
            pair_bar(bar_id);
        }

        if (s + 1 < NSTAGE) {
            cp_async_wait0();       // own cp.async groups done
            pair_bar(bar_id);       // partner's half of the stage done too
            buf ^= 1;
        }
    }

    // ---- final h: this warp's unit half, reconstructed hi+lo ----
#pragma unroll
    for (int it = 0; it < 4; it++) {
        int idx = it * 32 + lane;       // 0..127 = 8 rows x 16 units
        int r   = idx >> 4;
        int u   = 16 * half + (idx & 15);
        float hi = __uint_as_float((u32)hhi[pair][r][u] << 16);
        float lo = __uint_as_float((u32)hlo[pair][r][u] << 16);
        out[(size_t)(row0 + r) * HDIM + u] = hi + lo;
    }
}

extern "C" void kernel_launch(void* const* d_in, const int* in_sizes, int n_in,
                              void* d_out, int out_size)
{
    const float* x    = (const float*)d_in[0];
    const float* W_ih = (const float*)d_in[1];
    const float* W_hh = (const float*)d_in[2];
    const float* b_ih = (const float*)d_in[3];
    const float* b_hh = (const float*)d_in[4];
    float* out = (float*)d_out;

    // 256 blocks x 128 threads: 1024 warps (pairs of unit-halves), 16 rows
    // per block; 2 blocks/SM co-resident -> 2 warps per SMSP.
    lstm_mma_kernel<<<BATCH / (NPAIR * ROWS), 128>>>(
        x, W_ih, W_hh, b_ih, b_hh, out);
}